// round 15
// baseline (speedup 1.0000x reference)
#include <cuda_runtime.h>
#include <cuda_bf16.h>
#include <cstdint>

// Problem constants
#define BATCH   32
#define NN      64
#define DD      512
#define MM      2080          // N*(N+1)/2
#define SORTN   4096
#define NTHR    512
#define TOPK    5
#define NEIGH   16
#define NEGK    16
#define TOTALS  85            // TOPK*(NEIGH+1)
#define KK      101           // NEGK + TOTALS
#define NSEG    65            // 2080/32 exact

// Output layout (concatenated float32): feat, pred_s_e, offset, score
#define FEAT_BASE 0
#define SE_BASE   (BATCH*KK*DD)
#define OFF_BASE  (SE_BASE + BATCH*KK*2)
#define SC_BASE   (OFF_BASE + BATCH*KK*2)

typedef unsigned long long u64;
typedef unsigned int u32;
typedef unsigned short u16;

__device__ u64 g_keys[BATCH * SORTN];               // 1MB sort scratch

__device__ __forceinline__ u32 float_desc_key(float s) {
    u32 u = __float_as_uint(s);
    u32 k = (u & 0x80000000u) ? ~u : (u | 0x80000000u); // ascending map
    return ~k;                                          // descending
}

__device__ __forceinline__ u64 u64min(u64 a, u64 b) { return a < b ? a : b; }
__device__ __forceinline__ u64 u64max(u64 a, u64 b) { return a > b ? a : b; }

__device__ __forceinline__ void cswap(u64 &a, u64 &b, bool up) {
    if ((a > b) == up) { u64 t = a; a = b; b = t; }
}

__device__ __forceinline__ u32 warp_incl_scan(u32 v, int lane) {
    #pragma unroll
    for (int o = 1; o < 32; o <<= 1) {
        u32 t = __shfl_up_sync(0xFFFFFFFFu, v, o);
        if (lane >= o) v += t;
    }
    return v;
}

// lowest `rem` set bits of w
__device__ __forceinline__ u32 low_bits(u32 w, int rem) {
    if (rem <= 0) return 0;
    if (__popc(w) <= rem) return w;
    u32 x = w;
    #pragma unroll
    for (int q = 0; q < NEIGH; ++q)
        if (q < rem) x &= (x - 1);
    return w ^ x;
}

// mask of bits t in segment s whose global index s*32+t >= i
__device__ __forceinline__ u32 mask_ge(int s, int i) {
    int off = i - s * 32;
    if (off <= 0) return 0xFFFFFFFFu;
    if (off >= 32) return 0u;
    return 0xFFFFFFFFu << off;
}

// IoU>0.5 bits for two packed moments in word w vs (si,ei), bit positions 2wq,2wq+1
__device__ __forceinline__ u32 iou2(u32 w, int si, int ei, int wq) {
    u32 m = 0;
    #pragma unroll
    for (int h = 0; h < 2; ++h) {
        u32 mm = (h ? (w >> 16) : w) & 0xFFFFu;
        int s3 = (int)(mm & 0xFF), e3 = (int)(mm >> 8);
        int inter = min(e3, ei) - max(s3, si);
        int uni   = max(e3, ei) - min(s3, si);
        m |= ((u32)(2 * inter > uni)) << (2 * wq + h);   // uni>0 always; inter<=0 -> false
    }
    return m;
}

// 2-elem warp-local bitonic stages; eg = GLOBAL index of K[0], K[1] at eg+32.
__device__ __forceinline__ void reg_phase2(u64 K[2], int k, int jstart, int eg) {
    int j = jstart;
    if (j >= 32) {
        bool up = ((eg & k) == 0);
        cswap(K[0], K[1], up);
        j = 16;
    }
    for (; j >= 1; j >>= 1) {
        #pragma unroll
        for (int q = 0; q < 2; ++q) {
            int e = eg + q * 32;
            bool up = ((e & k) == 0);
            u64 o = __shfl_xor_sync(0xFFFFFFFFu, K[q], j);
            bool upper = (e & j) != 0;
            K[q] = (up != upper) ? u64min(K[q], o) : u64max(K[q], o);
        }
    }
}

// 8-elem warp-local bitonic stages; K[q] at ebase + q*32, ebase = warp*256+lane.
__device__ __forceinline__ void reg_phase8(u64 K[8], int k, int jstart, int ebase) {
    int j = jstart;
    if (j >= 128) {
        #pragma unroll
        for (int q = 0; q < 4; ++q) {
            bool up = (((ebase + q * 32) & k) == 0);
            cswap(K[q], K[q + 4], up);
        }
        j = 64;
    }
    if (j >= 64) {
        #pragma unroll
        for (int h = 0; h < 8; h += 4)
            #pragma unroll
            for (int q = 0; q < 2; ++q) {
                bool up = (((ebase + (h + q) * 32) & k) == 0);
                cswap(K[h + q], K[h + q + 2], up);
            }
        j = 32;
    }
    if (j >= 32) {
        #pragma unroll
        for (int q = 0; q < 8; q += 2) {
            bool up = (((ebase + q * 32) & k) == 0);
            cswap(K[q], K[q + 1], up);
        }
        j = 16;
    }
    for (; j >= 1; j >>= 1) {
        #pragma unroll
        for (int q = 0; q < 8; ++q) {
            int e = ebase + q * 32;
            bool up = ((e & k) == 0);
            u64 o = __shfl_xor_sync(0xFFFFFFFFu, K[q], j);
            bool upper = (e & j) != 0;
            K[q] = (up != upper) ? u64min(K[q], o) : u64max(K[q], o);
        }
    }
}

// ---------------------------------------------------------------------------
// Kernel 1: per-quarter bitonic, stages k = 2..1024 (proven R12 version).
// ---------------------------------------------------------------------------
__global__ void __launch_bounds__(NTHR, 2)
presort_kernel(const float* __restrict__ score_pred)
{
    __shared__ u64 sk[1024];                        // 8KB

    const int cta  = blockIdx.x;                    // b*4 + q
    const int b    = cta >> 2;
    const int qq   = cta & 3;
    const int tid  = threadIdx.x;
    const int lane = tid & 31;
    const int warp = tid >> 5;
    const int ebase = warp * 64 + lane;
    const int eg    = qq * 1024 + ebase;

    sk[tid] = ~0ULL; sk[tid + 512] = ~0ULL;
    __syncthreads();
    const int elo = qq * 1024, ehi = elo + 1024;
    #pragma unroll
    for (int idx = tid; idx < NN * NN; idx += NTHR) {
        int r = idx >> 6, c = idx & 63;
        if (c >= r) {
            int e = (r * (129 - r)) / 2 + (c - r);
            if (e >= elo && e < ehi) {
                float s = score_pred[b * (NN * NN) + idx];
                sk[e - elo] = ((u64)float_desc_key(s) << 32) | (u32)e;
            }
        }
    }
    __syncthreads();

    u64 K[2];
    K[0] = sk[ebase]; K[1] = sk[ebase + 32];

    for (int k = 2; k <= 64; k <<= 1)
        reg_phase2(K, k, (k >> 1) > 32 ? 32 : (k >> 1), eg);

    // k=128
    sk[ebase] = K[0]; sk[ebase + 32] = K[1];
    __syncthreads();
    {
        int i = ((tid & ~63) << 1) | (tid & 63);
        int p = i | 64;
        bool up = ((i & 128) == 0);
        u64 a = sk[i], c2 = sk[p];
        if ((a > c2) == up) { sk[i] = c2; sk[p] = a; }
    }
    __syncthreads();
    K[0] = sk[ebase]; K[1] = sk[ebase + 32];
    reg_phase2(K, 128, 32, eg);

    // k=256: fused2 (128,64)
    sk[ebase] = K[0]; sk[ebase + 32] = K[1];
    __syncthreads();
    if (tid < 256) {
        int base = ((tid & ~63) << 2) | (tid & 63);
        bool up = ((base & 256) == 0);
        u64 a0 = sk[base], a1 = sk[base + 64], a2 = sk[base + 128], a3 = sk[base + 192];
        cswap(a0, a2, up); cswap(a1, a3, up);
        cswap(a0, a1, up); cswap(a2, a3, up);
        sk[base] = a0; sk[base + 64] = a1; sk[base + 128] = a2; sk[base + 192] = a3;
    }
    __syncthreads();
    K[0] = sk[ebase]; K[1] = sk[ebase + 32];
    reg_phase2(K, 256, 32, eg);

    // k=512: fused3 (256,128,64)
    sk[ebase] = K[0]; sk[ebase + 32] = K[1];
    __syncthreads();
    if (tid < 128) {
        int base = ((tid & ~63) << 3) | (tid & 63);
        bool up = ((base & 512) == 0);
        u64 a[8];
        #pragma unroll
        for (int m = 0; m < 8; ++m) a[m] = sk[base + m * 64];
        #pragma unroll
        for (int m = 0; m < 4; ++m) cswap(a[m], a[m + 4], up);
        cswap(a[0], a[2], up); cswap(a[1], a[3], up);
        cswap(a[4], a[6], up); cswap(a[5], a[7], up);
        #pragma unroll
        for (int m = 0; m < 8; m += 2) cswap(a[m], a[m + 1], up);
        #pragma unroll
        for (int m = 0; m < 8; ++m) sk[base + m * 64] = a[m];
    }
    __syncthreads();
    K[0] = sk[ebase]; K[1] = sk[ebase + 32];
    reg_phase2(K, 512, 32, eg);

    // k=1024: fused2 (512,256) + fused2 (128,64) + tail
    const bool qup = ((qq & 1) == 0);
    sk[ebase] = K[0]; sk[ebase + 32] = K[1];
    __syncthreads();
    if (tid < 256) {
        int base = tid;
        u64 a0 = sk[base], a1 = sk[base + 256], a2 = sk[base + 512], a3 = sk[base + 768];
        cswap(a0, a2, qup); cswap(a1, a3, qup);
        cswap(a0, a1, qup); cswap(a2, a3, qup);
        sk[base] = a0; sk[base + 256] = a1; sk[base + 512] = a2; sk[base + 768] = a3;
    }
    __syncthreads();
    if (tid < 256) {
        int base = ((tid & ~63) << 2) | (tid & 63);
        u64 a0 = sk[base], a1 = sk[base + 64], a2 = sk[base + 128], a3 = sk[base + 192];
        cswap(a0, a2, qup); cswap(a1, a3, qup);
        cswap(a0, a1, qup); cswap(a2, a3, qup);
        sk[base] = a0; sk[base + 64] = a1; sk[base + 128] = a2; sk[base + 192] = a3;
    }
    __syncthreads();
    K[0] = sk[ebase]; K[1] = sk[ebase + 32];
    reg_phase2(K, 1024, 32, eg);

    g_keys[cta * 1024 + ebase]      = K[0];
    g_keys[cta * 1024 + ebase + 32] = K[1];
}

// ---------------------------------------------------------------------------
// Kernel 2: merge k=2048/4096 + single-warp register NMS + outputs + gather.
// ---------------------------------------------------------------------------
__global__ void __launch_bounds__(NTHR, 1)
merge_select_kernel(const float* __restrict__ map2d,
                    const float* __restrict__ offset_gt,
                    const float* __restrict__ tmap,
                    float* __restrict__ out)
{
    __shared__ u64 skeys[SORTN];                    // 32768 B
    __shared__ u16 rc[MM];
    __shared__ __align__(16) u16 smom[MM];
    __shared__ u32 maskw[NSEG], supw[NSEG], selw[NSEG];
    __shared__ u16 unsup_idx[MM];
    __shared__ u16 sel_idx[TOTALS];
    __shared__ u32 upref[NSEG + 1], spref[NSEG + 1];
    __shared__ u32 s_sel[KK];

    const int b    = blockIdx.x;
    const int tid  = threadIdx.x;
    const int lane = tid & 31;
    const int warp = tid >> 5;
    const int ebase = warp * 256 + lane;

    // ---- load sorted runs (uint4, MLP=4) + build rc table ----
    {
        const uint4* gk4 = (const uint4*)(g_keys + (size_t)b * SORTN);
        uint4* sk4 = (uint4*)skeys;
        #pragma unroll
        for (int i = tid; i < SORTN / 2; i += NTHR) sk4[i] = gk4[i];
    }
    #pragma unroll
    for (int idx = tid; idx < NN * NN; idx += NTHR) {
        int r = idx >> 6, c = idx & 63;
        if (c >= r) {
            int e = (r * (129 - r)) / 2 + (c - r);
            rc[e] = (u16)(r | (c << 8));
        }
    }
    __syncthreads();

    // ---- k = 2048: fused3 (1024,512,256), warp tail ----
    u64 K[8];
    {
        int base = ((tid & ~255) << 3) | (tid & 255);
        bool up = ((base & 2048) == 0);
        u64 a[8];
        #pragma unroll
        for (int m = 0; m < 8; ++m) a[m] = skeys[base + m * 256];
        #pragma unroll
        for (int m = 0; m < 4; ++m) cswap(a[m], a[m + 4], up);      // j=1024
        cswap(a[0], a[2], up); cswap(a[1], a[3], up);               // j=512
        cswap(a[4], a[6], up); cswap(a[5], a[7], up);
        #pragma unroll
        for (int m = 0; m < 8; m += 2) cswap(a[m], a[m + 1], up);   // j=256
        #pragma unroll
        for (int m = 0; m < 8; ++m) skeys[base + m * 256] = a[m];
    }
    __syncthreads();
    #pragma unroll
    for (int q = 0; q < 8; ++q) K[q] = skeys[ebase + q * 32];
    reg_phase8(K, 2048, 128, ebase);

    // ---- k = 4096: fused4 (2048,1024,512,256), warp tail ----
    #pragma unroll
    for (int q = 0; q < 8; ++q) skeys[ebase + q * 32] = K[q];
    __syncthreads();
    if (tid < 256) {
        int base = tid;
        u64 a[16];
        #pragma unroll
        for (int m = 0; m < 16; ++m) a[m] = skeys[base + m * 256];
        #pragma unroll
        for (int m = 0; m < 8; ++m) cswap(a[m], a[m + 8], true);    // j=2048
        #pragma unroll
        for (int h2 = 0; h2 < 16; h2 += 8)
            #pragma unroll
            for (int m = 0; m < 4; ++m) cswap(a[h2 + m], a[h2 + m + 4], true); // j=1024
        #pragma unroll
        for (int h2 = 0; h2 < 16; h2 += 4) {
            cswap(a[h2], a[h2 + 2], true); cswap(a[h2 + 1], a[h2 + 3], true);  // j=512
        }
        #pragma unroll
        for (int m = 0; m < 16; m += 2) cswap(a[m], a[m + 1], true);           // j=256
        #pragma unroll
        for (int m = 0; m < 16; ++m) skeys[base + m * 256] = a[m];
    }
    __syncthreads();
    #pragma unroll
    for (int q = 0; q < 8; ++q) K[q] = skeys[ebase + q * 32];
    reg_phase8(K, 4096, 128, ebase);
    #pragma unroll
    for (int q = 0; q < 8; ++q) skeys[ebase + q * 32] = K[q];
    __syncthreads();

    // ---- Phase C: moments + pick-0 ballot + default fills ----
    u32 mreg[5];
    #pragma unroll
    for (int rd = 0; rd < 5; ++rd) {
        int i = tid + rd * NTHR;
        u32 v = 0;
        if (i < MM) {
            u32 e = (u32)skeys[i];
            u32 rcv = rc[e];
            int s = rcv & 0xFF;
            int en = (rcv >> 8) + 1;
            v = (u32)(s | (en << 8));
            smom[i] = (u16)v;
        }
        mreg[rd] = v;
    }
    __syncthreads();                    // smom & skeys[0] final

    // pick-0 IoU ballot (rank 0 is always the first pick)
    {
        u32 e0 = (u32)skeys[0];
        u32 r0v = rc[e0];
        int si0 = (int)(r0v & 0xFF), ei0 = (int)(r0v >> 8) + 1;
        #pragma unroll
        for (int rd = 0; rd < 5; ++rd) {
            int e2 = tid + rd * NTHR;
            bool mk = false;
            if (e2 > 0 && e2 < MM) {
                u32 mmv = mreg[rd];
                int s3 = (int)(mmv & 0xFF), e3 = (int)(mmv >> 8);
                int inter = min(e3, ei0) - max(s3, si0);
                int uni   = max(e3, ei0) - min(s3, si0);
                mk = (2 * inter > uni);
            }
            u32 bal = __ballot_sync(0xFFFFFFFFu, mk);
            int seg = warp + rd * 16;
            if (lane == 0 && seg < NSEG) maskw[seg] = bal;
        }
    }
    // default fills (overlap with NMS warp's setup)
    #pragma unroll
    for (int t = tid; t < MM; t += NTHR) unsup_idx[t] = (u16)(MM - 1);
    if (tid >= NTHR - TOTALS) sel_idx[tid - (NTHR - TOTALS)] = (u16)(MM - 1);
    __syncthreads();

    // ---- single-warp register NMS (warp 0; no barriers inside) ----
    if (warp == 0) {
        // cache moments of segs lane, lane+32 as packed u32 pairs
        u32 MA[16], MB[16];
        {
            const uint4* pa = (const uint4*)(smom + lane * 32);
            const uint4* pb = (const uint4*)(smom + (lane + 32) * 32);
            #pragma unroll
            for (int g = 0; g < 4; ++g) {
                uint4 va = pa[g];
                MA[g*4+0] = va.x; MA[g*4+1] = va.y; MA[g*4+2] = va.z; MA[g*4+3] = va.w;
                uint4 vb = pb[g];
                MB[g*4+0] = vb.x; MB[g*4+1] = vb.y; MB[g*4+2] = vb.z; MB[g*4+3] = vb.w;
            }
        }
        u32 sup_a, sup_b, sup_c = 0, sel_a, sel_b, sel_c = 0;

        // fold pick 0 from precomputed ballots
        {
            u32 m0 = maskw[lane];
            u32 m1 = maskw[lane + 32];
            u32 m2 = (lane == 0) ? maskw[64] : 0;
            u32 v0 = __popc(m0), v1 = __popc(m1);
            u32 s0 = warp_incl_scan(v0, lane);
            u32 t0 = __shfl_sync(0xFFFFFFFFu, s0, 31);
            u32 s1 = warp_incl_scan(v1, lane) + t0;
            u32 pre0 = s0 - v0, pre1 = s1 - v1;
            u32 pre2 = __shfl_sync(0xFFFFFFFFu, s1, 31);
            sup_a = m0; sup_b = m1;
            u32 add = low_bits(m0, NEIGH - (int)pre0);
            if (lane == 0) { sup_a |= 1u; sup_c = m2; add |= 1u; }
            sel_a = add;
            sel_b = low_bits(m1, NEIGH - (int)pre1);
            if (lane == 0) sel_c = low_bits(m2, NEIGH - (int)pre2);
        }

        int i = 1, cnt = 1;
        while (cnt < TOPK) {
            // find next free index >= i (register masks + shfl-min)
            int cand = 0x7FFFFFFF;
            u32 f = ~sup_a & mask_ge(lane, i);
            if (f) cand = lane * 32 + __ffs(f) - 1;
            f = ~sup_b & mask_ge(lane + 32, i);
            if (f) cand = min(cand, (lane + 32) * 32 + __ffs(f) - 1);
            if (lane == 0) {
                f = ~sup_c & mask_ge(64, i);
                if (f) cand = min(cand, 2048 + __ffs(f) - 1);
            }
            #pragma unroll
            for (int o = 16; o; o >>= 1)
                cand = min(cand, __shfl_xor_sync(0xFFFFFFFFu, cand, o));
            i = cand;
            if (i >= MM - 1) break;

            const int iseg = i >> 5;
            const u32 ibit = 1u << (i & 31);
            u32 mi = smom[i];                       // broadcast LDS
            int si = (int)(mi & 0xFF), ei = (int)(mi >> 8);

            // IoU masks from registers
            u32 m_a = 0, m_b = 0;
            #pragma unroll
            for (int wq = 0; wq < 16; ++wq) {
                m_a |= iou2(MA[wq], si, ei, wq);
                m_b |= iou2(MB[wq], si, ei, wq);
            }
            m_a &= mask_ge(lane, i + 1);            // keep only e2 > i
            m_b &= mask_ge(lane + 32, i + 1);
            u32 m_c = 0;
            if (lane == 0) {
                const uint4* pc = (const uint4*)(smom + 64 * 32);
                #pragma unroll
                for (int g = 0; g < 4; ++g) {
                    uint4 vc = pc[g];
                    m_c |= iou2(vc.x, si, ei, g * 4 + 0);
                    m_c |= iou2(vc.y, si, ei, g * 4 + 1);
                    m_c |= iou2(vc.z, si, ei, g * 4 + 2);
                    m_c |= iou2(vc.w, si, ei, g * 4 + 3);
                }
                m_c &= mask_ge(64, i + 1);
            }
            // neighbor sets exclude the pick bit; sup/sel include it
            u32 na = m_a, nbx = m_b, ncx = m_c;
            if (iseg == lane)            m_a |= ibit;
            else if (iseg == lane + 32)  m_b |= ibit;
            else if (lane == 0 && iseg == 64) m_c |= ibit;

            u32 v0 = __popc(na), v1 = __popc(nbx);
            u32 s0 = warp_incl_scan(v0, lane);
            u32 t0 = __shfl_sync(0xFFFFFFFFu, s0, 31);
            u32 s1 = warp_incl_scan(v1, lane) + t0;
            u32 pre0 = s0 - v0, pre1 = s1 - v1;
            u32 pre2 = __shfl_sync(0xFFFFFFFFu, s1, 31);

            sup_a |= m_a; sup_b |= m_b;
            if (lane == 0) sup_c |= m_c;

            u32 add = low_bits(na, NEIGH - (int)pre0);
            if (iseg == lane) add |= ibit;
            sel_a |= add;
            add = low_bits(nbx, NEIGH - (int)pre1);
            if (iseg == lane + 32) add |= ibit;
            sel_b |= add;
            if (lane == 0) {
                add = low_bits(ncx, NEIGH - (int)pre2);
                if (iseg == 64) add |= ibit;
                sel_c |= add;
            }
            ++i; ++cnt;
        }

        // publish final state + prefix sums
        supw[lane] = sup_a; supw[lane + 32] = sup_b;
        selw[lane] = sel_a; selw[lane + 32] = sel_b;
        if (lane == 0) { supw[64] = sup_c; selw[64] = sel_c; }

        {   // unsup prefix
            u32 v0 = __popc(~sup_a), v1 = __popc(~sup_b);
            u32 v2 = (lane == 0) ? __popc(~sup_c) : 0;
            u32 s0 = warp_incl_scan(v0, lane);
            u32 t0 = __shfl_sync(0xFFFFFFFFu, s0, 31);
            u32 s1 = warp_incl_scan(v1, lane) + t0;
            u32 t1 = __shfl_sync(0xFFFFFFFFu, s1, 31);
            upref[lane]      = s0 - v0;
            upref[lane + 32] = s1 - v1;
            if (lane == 0) { upref[64] = t1; upref[65] = t1 + v2; }
        }
        {   // sel prefix
            u32 v0 = __popc(sel_a), v1 = __popc(sel_b);
            u32 v2 = (lane == 0) ? __popc(sel_c) : 0;
            u32 s0 = warp_incl_scan(v0, lane);
            u32 t0 = __shfl_sync(0xFFFFFFFFu, s0, 31);
            u32 s1 = warp_incl_scan(v1, lane) + t0;
            u32 t1 = __shfl_sync(0xFFFFFFFFu, s1, 31);
            spref[lane]      = s0 - v0;
            spref[lane + 32] = s1 - v1;
            if (lane == 0) { spref[64] = t1; spref[65] = t1 + v2; }
        }
    }
    __syncthreads();

    // ---- scatter compaction ----
    #pragma unroll
    for (int e2 = tid; e2 < MM; e2 += NTHR) {
        int s2 = e2 >> 5;
        u32 bit = 1u << (e2 & 31);
        u32 low = bit - 1u;
        u32 uw = ~supw[s2];
        if (uw & bit) unsup_idx[upref[s2] + __popc(uw & low)] = (u16)e2;
        u32 sw = selw[s2];
        if (sw & bit) sel_idx[spref[s2] + __popc(sw & low)] = (u16)e2;
    }
    __syncthreads();

    // ---- final index assembly + small outputs ----
    if (tid < KK) {
        int n_unsup = (int)upref[NSEG];
        int n_sel   = (int)spref[NSEG];
        int pad     = TOTALS - n_sel;

        int idxS;
        if (tid < NEGK) {
            int t = n_unsup - 1 - tid;
            if (t < 0) t = 0;
            if (t > MM - 1) t = MM - 1;
            idxS = unsup_idx[t];
        } else {
            int p = tid - NEGK;
            if (p < pad) idxS = unsup_idx[p];
            else {
                int q = p - pad;
                if (q > TOTALS - 1) q = TOTALS - 1;
                idxS = sel_idx[q];
            }
        }
        u32 orig = (u32)skeys[idxS];
        u32 rcv  = rc[orig];
        int r = rcv & 0xFF;
        int c = rcv >> 8;

        int gk = b * KK + tid;
        s_sel[tid] = (u32)(r * NN + c);

        out[SE_BASE + gk * 2 + 0] = (float)r;
        out[SE_BASE + gk * 2 + 1] = (float)(c + 1);

        size_t oidx = ((size_t)(b * NN + r) * NN + c) * 2;
        out[OFF_BASE + gk * 2 + 0] = offset_gt[oidx + 0];
        out[OFF_BASE + gk * 2 + 1] = offset_gt[oidx + 1];

        out[SC_BASE + gk] = tmap[(size_t)(b * NN + r) * NN + c];
    }
    __syncthreads();

    // ---- feature gather: batched loads (3 rounds of <=9 outstanding) ----
    {
        const float4* __restrict__ src4 = (const float4*)map2d;
        float4* __restrict__ dst4 = (float4*)(out + FEAT_BASE);
        const size_t bbase = (size_t)b * (NN * NN) * (DD / 4);
        const size_t obase = (size_t)b * KK * (DD / 4);
        const int total = KK * (DD / 4);            // 12928
        #pragma unroll 1
        for (int s0 = 0; s0 < 26; s0 += 9) {
            float4 v[9];
            #pragma unroll
            for (int m = 0; m < 9; ++m) {
                int s = s0 + m;
                int t = tid + s * NTHR;
                if (s < 26 && t < total) {
                    int row = t >> 7, q = t & 127;
                    v[m] = src4[bbase + (size_t)s_sel[row] * (DD / 4) + q];
                }
            }
            #pragma unroll
            for (int m = 0; m < 9; ++m) {
                int s = s0 + m;
                int t = tid + s * NTHR;
                if (s < 26 && t < total) {
                    int row = t >> 7, q = t & 127;
                    dst4[obase + (size_t)row * (DD / 4) + q] = v[m];
                }
            }
        }
    }
}

extern "C" void kernel_launch(void* const* d_in, const int* in_sizes, int n_in,
                              void* d_out, int out_size)
{
    const float* score_pred = (const float*)d_in[0];
    // d_in[1] = map2d_mask (deterministic triu — not needed)
    const float* map2d      = (const float*)d_in[2];
    const float* offset_gt  = (const float*)d_in[3];
    const float* tmap       = (const float*)d_in[4];
    float* out = (float*)d_out;

    presort_kernel<<<BATCH * 4, NTHR>>>(score_pred);
    merge_select_kernel<<<BATCH, NTHR>>>(map2d, offset_gt, tmap, out);
}

// round 16
// speedup vs baseline: 1.1590x; 1.1590x over previous
#include <cuda_runtime.h>
#include <cuda_bf16.h>
#include <cstdint>

// Problem constants
#define BATCH   32
#define NN      64
#define DD      512
#define MM      2080          // N*(N+1)/2
#define SORTN   4096
#define NTHR    512
#define TOPK    5
#define NEIGH   16
#define NEGK    16
#define TOTALS  85            // TOPK*(NEIGH+1)
#define KK      101           // NEGK + TOTALS
#define NSEG    65            // 2080/32 exact

// Output layout (concatenated float32): feat, pred_s_e, offset, score
#define FEAT_BASE 0
#define SE_BASE   (BATCH*KK*DD)
#define OFF_BASE  (SE_BASE + BATCH*KK*2)
#define SC_BASE   (OFF_BASE + BATCH*KK*2)

typedef unsigned long long u64;
typedef unsigned int u32;
typedef unsigned short u16;

__device__ u64 g_keys[BATCH * SORTN];               // 1MB sort scratch

__device__ __forceinline__ u32 float_desc_key(float s) {
    u32 u = __float_as_uint(s);
    u32 k = (u & 0x80000000u) ? ~u : (u | 0x80000000u); // ascending map
    return ~k;                                          // descending
}

__device__ __forceinline__ u64 u64min(u64 a, u64 b) { return a < b ? a : b; }
__device__ __forceinline__ u64 u64max(u64 a, u64 b) { return a > b ? a : b; }

__device__ __forceinline__ void cswap(u64 &a, u64 &b, bool up) {
    if ((a > b) == up) { u64 t = a; a = b; b = t; }
}

__device__ __forceinline__ u32 warp_incl_scan(u32 v, int lane) {
    #pragma unroll
    for (int o = 1; o < 32; o <<= 1) {
        u32 t = __shfl_up_sync(0xFFFFFFFFu, v, o);
        if (lane >= o) v += t;
    }
    return v;
}

// lowest `rem` set bits of w
__device__ __forceinline__ u32 low_bits(u32 w, int rem) {
    if (rem <= 0) return 0;
    if (__popc(w) <= rem) return w;
    u32 x = w;
    #pragma unroll
    for (int q = 0; q < NEIGH; ++q)
        if (q < rem) x &= (x - 1);
    return w ^ x;
}

// 2-elem warp-local bitonic stages; eg = GLOBAL index of K[0], K[1] at eg+32.
__device__ __forceinline__ void reg_phase2(u64 K[2], int k, int jstart, int eg) {
    int j = jstart;
    if (j >= 32) {
        bool up = ((eg & k) == 0);
        cswap(K[0], K[1], up);
        j = 16;
    }
    for (; j >= 1; j >>= 1) {
        #pragma unroll
        for (int q = 0; q < 2; ++q) {
            int e = eg + q * 32;
            bool up = ((e & k) == 0);
            u64 o = __shfl_xor_sync(0xFFFFFFFFu, K[q], j);
            bool upper = (e & j) != 0;
            K[q] = (up != upper) ? u64min(K[q], o) : u64max(K[q], o);
        }
    }
}

// 8-elem warp-local bitonic stages; K[q] at ebase + q*32, ebase = warp*256+lane.
__device__ __forceinline__ void reg_phase8(u64 K[8], int k, int jstart, int ebase) {
    int j = jstart;
    if (j >= 128) {
        #pragma unroll
        for (int q = 0; q < 4; ++q) {
            bool up = (((ebase + q * 32) & k) == 0);
            cswap(K[q], K[q + 4], up);
        }
        j = 64;
    }
    if (j >= 64) {
        #pragma unroll
        for (int h = 0; h < 8; h += 4)
            #pragma unroll
            for (int q = 0; q < 2; ++q) {
                bool up = (((ebase + (h + q) * 32) & k) == 0);
                cswap(K[h + q], K[h + q + 2], up);
            }
        j = 32;
    }
    if (j >= 32) {
        #pragma unroll
        for (int q = 0; q < 8; q += 2) {
            bool up = (((ebase + q * 32) & k) == 0);
            cswap(K[q], K[q + 1], up);
        }
        j = 16;
    }
    for (; j >= 1; j >>= 1) {
        #pragma unroll
        for (int q = 0; q < 8; ++q) {
            int e = ebase + q * 32;
            bool up = ((e & k) == 0);
            u64 o = __shfl_xor_sync(0xFFFFFFFFu, K[q], j);
            bool upper = (e & j) != 0;
            K[q] = (up != upper) ? u64min(K[q], o) : u64max(K[q], o);
        }
    }
}

// ---------------------------------------------------------------------------
// Kernel 1: per-quarter bitonic, stages k = 2..1024 (proven R12 version).
// ---------------------------------------------------------------------------
__global__ void __launch_bounds__(NTHR, 2)
presort_kernel(const float* __restrict__ score_pred)
{
    __shared__ u64 sk[1024];                        // 8KB

    const int cta  = blockIdx.x;                    // b*4 + q
    const int b    = cta >> 2;
    const int qq   = cta & 3;
    const int tid  = threadIdx.x;
    const int lane = tid & 31;
    const int warp = tid >> 5;
    const int ebase = warp * 64 + lane;
    const int eg    = qq * 1024 + ebase;

    sk[tid] = ~0ULL; sk[tid + 512] = ~0ULL;
    __syncthreads();
    const int elo = qq * 1024, ehi = elo + 1024;
    #pragma unroll
    for (int idx = tid; idx < NN * NN; idx += NTHR) {
        int r = idx >> 6, c = idx & 63;
        if (c >= r) {
            int e = (r * (129 - r)) / 2 + (c - r);
            if (e >= elo && e < ehi) {
                float s = score_pred[b * (NN * NN) + idx];
                sk[e - elo] = ((u64)float_desc_key(s) << 32) | (u32)e;
            }
        }
    }
    __syncthreads();

    u64 K[2];
    K[0] = sk[ebase]; K[1] = sk[ebase + 32];

    for (int k = 2; k <= 64; k <<= 1)
        reg_phase2(K, k, (k >> 1) > 32 ? 32 : (k >> 1), eg);

    // k=128: smem j=64
    sk[ebase] = K[0]; sk[ebase + 32] = K[1];
    __syncthreads();
    {
        int i = ((tid & ~63) << 1) | (tid & 63);
        int p = i | 64;
        bool up = ((i & 128) == 0);
        u64 a = sk[i], c2 = sk[p];
        if ((a > c2) == up) { sk[i] = c2; sk[p] = a; }
    }
    __syncthreads();
    K[0] = sk[ebase]; K[1] = sk[ebase + 32];
    reg_phase2(K, 128, 32, eg);

    // k=256: fused2 (128,64)
    sk[ebase] = K[0]; sk[ebase + 32] = K[1];
    __syncthreads();
    if (tid < 256) {
        int base = ((tid & ~63) << 2) | (tid & 63);
        bool up = ((base & 256) == 0);
        u64 a0 = sk[base], a1 = sk[base + 64], a2 = sk[base + 128], a3 = sk[base + 192];
        cswap(a0, a2, up); cswap(a1, a3, up);
        cswap(a0, a1, up); cswap(a2, a3, up);
        sk[base] = a0; sk[base + 64] = a1; sk[base + 128] = a2; sk[base + 192] = a3;
    }
    __syncthreads();
    K[0] = sk[ebase]; K[1] = sk[ebase + 32];
    reg_phase2(K, 256, 32, eg);

    // k=512: fused3 (256,128,64)
    sk[ebase] = K[0]; sk[ebase + 32] = K[1];
    __syncthreads();
    if (tid < 128) {
        int base = ((tid & ~63) << 3) | (tid & 63);
        bool up = ((base & 512) == 0);
        u64 a[8];
        #pragma unroll
        for (int m = 0; m < 8; ++m) a[m] = sk[base + m * 64];
        #pragma unroll
        for (int m = 0; m < 4; ++m) cswap(a[m], a[m + 4], up);
        cswap(a[0], a[2], up); cswap(a[1], a[3], up);
        cswap(a[4], a[6], up); cswap(a[5], a[7], up);
        #pragma unroll
        for (int m = 0; m < 8; m += 2) cswap(a[m], a[m + 1], up);
        #pragma unroll
        for (int m = 0; m < 8; ++m) sk[base + m * 64] = a[m];
    }
    __syncthreads();
    K[0] = sk[ebase]; K[1] = sk[ebase + 32];
    reg_phase2(K, 512, 32, eg);

    // k=1024: fused2 (512,256) + fused2 (128,64) + tail
    const bool qup = ((qq & 1) == 0);
    sk[ebase] = K[0]; sk[ebase + 32] = K[1];
    __syncthreads();
    if (tid < 256) {
        int base = tid;
        u64 a0 = sk[base], a1 = sk[base + 256], a2 = sk[base + 512], a3 = sk[base + 768];
        cswap(a0, a2, qup); cswap(a1, a3, qup);
        cswap(a0, a1, qup); cswap(a2, a3, qup);
        sk[base] = a0; sk[base + 256] = a1; sk[base + 512] = a2; sk[base + 768] = a3;
    }
    __syncthreads();
    if (tid < 256) {
        int base = ((tid & ~63) << 2) | (tid & 63);
        u64 a0 = sk[base], a1 = sk[base + 64], a2 = sk[base + 128], a3 = sk[base + 192];
        cswap(a0, a2, qup); cswap(a1, a3, qup);
        cswap(a0, a1, qup); cswap(a2, a3, qup);
        sk[base] = a0; sk[base + 64] = a1; sk[base + 128] = a2; sk[base + 192] = a3;
    }
    __syncthreads();
    K[0] = sk[ebase]; K[1] = sk[ebase + 32];
    reg_phase2(K, 1024, 32, eg);

    g_keys[cta * 1024 + ebase]      = K[0];
    g_keys[cta * 1024 + ebase + 32] = K[1];
}

// ---------------------------------------------------------------------------
// Kernel 2: merge k=2048, k=4096 + NMS + compaction + outputs + gather.
// (R12 structure + uint4 loads + pick-0 precompute + batched gather)
// ---------------------------------------------------------------------------
__global__ void __launch_bounds__(NTHR, 1)
merge_select_kernel(const float* __restrict__ map2d,
                    const float* __restrict__ offset_gt,
                    const float* __restrict__ tmap,
                    float* __restrict__ out)
{
    __shared__ u64 skeys[SORTN];                    // 32768 B
    __shared__ u16 rc[MM];
    __shared__ u16 smom[MM];
    __shared__ u32 maskw[NSEG], supw[NSEG], selw[NSEG];
    __shared__ u16 unsup_idx[MM];
    __shared__ u16 sel_idx[TOTALS];
    __shared__ u32 upref[NSEG + 1], spref[NSEG + 1];
    __shared__ u32 s_sel[KK];

    const int b    = blockIdx.x;
    const int tid  = threadIdx.x;
    const int lane = tid & 31;
    const int warp = tid >> 5;
    const int ebase = warp * 256 + lane;

    // ---- load sorted runs (uint4, MLP x2) + build rc table ----
    {
        const uint4* gk4 = (const uint4*)(g_keys + (size_t)b * SORTN);
        uint4* sk4 = (uint4*)skeys;
        #pragma unroll
        for (int i = tid; i < SORTN / 2; i += NTHR) sk4[i] = gk4[i];
    }
    #pragma unroll
    for (int idx = tid; idx < NN * NN; idx += NTHR) {
        int r = idx >> 6, c = idx & 63;
        if (c >= r) {
            int e = (r * (129 - r)) / 2 + (c - r);
            rc[e] = (u16)(r | (c << 8));
        }
    }
    __syncthreads();

    // ---- k = 2048: fused3 (1024,512,256), warp tail ----
    u64 K[8];
    {
        int base = ((tid & ~255) << 3) | (tid & 255);
        bool up = ((base & 2048) == 0);
        u64 a[8];
        #pragma unroll
        for (int m = 0; m < 8; ++m) a[m] = skeys[base + m * 256];
        #pragma unroll
        for (int m = 0; m < 4; ++m) cswap(a[m], a[m + 4], up);      // j=1024
        cswap(a[0], a[2], up); cswap(a[1], a[3], up);               // j=512
        cswap(a[4], a[6], up); cswap(a[5], a[7], up);
        #pragma unroll
        for (int m = 0; m < 8; m += 2) cswap(a[m], a[m + 1], up);   // j=256
        #pragma unroll
        for (int m = 0; m < 8; ++m) skeys[base + m * 256] = a[m];
    }
    __syncthreads();
    #pragma unroll
    for (int q = 0; q < 8; ++q) K[q] = skeys[ebase + q * 32];
    reg_phase8(K, 2048, 128, ebase);

    // ---- k = 4096: fused4 (2048,1024,512,256), warp tail ----
    #pragma unroll
    for (int q = 0; q < 8; ++q) skeys[ebase + q * 32] = K[q];
    __syncthreads();
    if (tid < 256) {
        int base = tid;
        u64 a[16];
        #pragma unroll
        for (int m = 0; m < 16; ++m) a[m] = skeys[base + m * 256];
        #pragma unroll
        for (int m = 0; m < 8; ++m) cswap(a[m], a[m + 8], true);    // j=2048
        #pragma unroll
        for (int h2 = 0; h2 < 16; h2 += 8)
            #pragma unroll
            for (int m = 0; m < 4; ++m) cswap(a[h2 + m], a[h2 + m + 4], true); // j=1024
        #pragma unroll
        for (int h2 = 0; h2 < 16; h2 += 4) {
            cswap(a[h2], a[h2 + 2], true); cswap(a[h2 + 1], a[h2 + 3], true);  // j=512
        }
        #pragma unroll
        for (int m = 0; m < 16; m += 2) cswap(a[m], a[m + 1], true);           // j=256
        #pragma unroll
        for (int m = 0; m < 16; ++m) skeys[base + m * 256] = a[m];
    }
    __syncthreads();
    #pragma unroll
    for (int q = 0; q < 8; ++q) K[q] = skeys[ebase + q * 32];
    reg_phase8(K, 4096, 128, ebase);
    #pragma unroll
    for (int q = 0; q < 8; ++q) skeys[ebase + q * 32] = K[q];
    __syncthreads();

    // ---- Phase C: sorted moments + pick-0 ballot (rank 0 always first pick) ----
    u32 mreg[5];
    #pragma unroll
    for (int rd = 0; rd < 5; ++rd) {
        int i = tid + rd * NTHR;
        u32 v = 0;
        if (i < MM) {
            u32 e = (u32)skeys[i];
            u32 rcv = rc[e];
            int s = rcv & 0xFF;
            int en = (rcv >> 8) + 1;
            v = (u32)(s | (en << 8));
            smom[i] = (u16)v;
        }
        mreg[rd] = v;
    }
    // pick-0 IoU ballots (skeys/rc are final; mreg in registers)
    {
        u32 e0 = (u32)skeys[0];
        u32 r0v = rc[e0];
        int si0 = (int)(r0v & 0xFF), ei0 = (int)(r0v >> 8) + 1;
        #pragma unroll
        for (int rd = 0; rd < 5; ++rd) {
            int e2 = tid + rd * NTHR;
            bool mk = false;
            if (e2 > 0 && e2 < MM) {
                u32 mmv = mreg[rd];
                int s3 = (int)(mmv & 0xFF), e3 = (int)(mmv >> 8);
                int inter = min(e3, ei0) - max(s3, si0);
                int uni   = max(e3, ei0) - min(s3, si0);
                mk = (inter > 0) && (2 * inter > uni);
            }
            u32 bal = __ballot_sync(0xFFFFFFFFu, mk);
            int seg = warp + rd * 16;
            if (lane == 0 && seg < NSEG) maskw[seg] = bal;
        }
    }
    if (tid < NSEG) { supw[tid] = 0u; selw[tid] = 0u; }
    __syncthreads();

    // ---- fold pick 0 (warp 0), same update code as loop body with i=0 ----
    if (warp == 0) {
        u32 full0 = maskw[lane];
        if (lane == 0) full0 |= 1u;                 // bit 0 = the pick itself
        u32 full1 = maskw[lane + 32];
        u32 full2 = (lane == 0) ? maskw[64] : 0;
        u32 m0 = full0;
        if (lane == 0) m0 &= ~1u;                   // neighbors exclude pick bit
        u32 m1 = full1, m2 = full2;
        u32 v0 = __popc(m0), v1 = __popc(m1);
        u32 s0 = warp_incl_scan(v0, lane);
        u32 t0 = __shfl_sync(0xFFFFFFFFu, s0, 31);
        u32 s1 = warp_incl_scan(v1, lane) + t0;
        u32 nb0 = s0 - v0;
        u32 nb1 = s1 - v1;
        u32 nb2 = __shfl_sync(0xFFFFFFFFu, s1, 31);
        supw[lane]      |= full0;
        supw[lane + 32] |= full1;
        if (lane == 0) supw[64] |= full2;
        u32 add0 = low_bits(m0, NEIGH - (int)nb0);
        if (lane == 0) add0 |= 1u;
        if (add0) selw[lane] |= add0;
        u32 add1 = low_bits(m1, NEIGH - (int)nb1);
        if (add1) selw[lane + 32] |= add1;
        if (lane == 0) {
            u32 add2 = low_bits(m2, NEIGH - (int)nb2);
            if (add2) selw[64] |= add2;
        }
    }
    __syncthreads();

    // ---- greedy NMS: remaining picks (2 barriers/iter) ----
    {
        int i = 1, cnt = 1;
        while (cnt < TOPK) {
            {
                int s2 = i >> 5;
                u32 w = (~supw[s2]) & (0xFFFFFFFFu << (i & 31));
                while (w == 0 && s2 < NSEG - 1) { ++s2; w = ~supw[s2]; }
                i = w ? (s2 * 32 + __ffs(w) - 1) : MM;
            }
            if (i >= MM - 1) break;

            const int iseg = i >> 5;
            const u32 ibit = 1u << (i & 31);
            u32 mi = smom[i];
            int si = mi & 0xFF, ei = mi >> 8;

            #pragma unroll
            for (int rd = 0; rd < 5; ++rd) {
                int e2 = tid + rd * NTHR;
                bool mk = false;
                if (e2 < MM) {
                    if (e2 == i) mk = true;
                    else if (e2 > i) {
                        u32 mmv = mreg[rd];
                        int s3 = mmv & 0xFF, e3 = mmv >> 8;
                        int inter = min(e3, ei) - max(s3, si);
                        if (inter > 0) {
                            int uni = max(e3, ei) - min(s3, si);
                            mk = (2 * inter > uni);
                        }
                    }
                }
                u32 bal = __ballot_sync(0xFFFFFFFFu, mk);
                int seg = warp + rd * 16;
                if (lane == 0 && seg < NSEG) maskw[seg] = bal;
            }
            __syncthreads();

            if (warp == 0) {
                u32 full0 = maskw[lane];
                u32 full1 = maskw[lane + 32];
                u32 full2 = (lane == 0) ? maskw[64] : 0;
                u32 m0 = full0, m1 = full1, m2 = full2;
                if (lane == iseg)        m0 &= ~ibit;
                if (lane + 32 == iseg)   m1 &= ~ibit;
                if (lane == 0 && iseg == 64) m2 &= ~ibit;
                u32 v0 = __popc(m0), v1 = __popc(m1);
                u32 s0 = warp_incl_scan(v0, lane);
                u32 t0 = __shfl_sync(0xFFFFFFFFu, s0, 31);
                u32 s1 = warp_incl_scan(v1, lane) + t0;
                u32 nb0 = s0 - v0;
                u32 nb1 = s1 - v1;
                u32 nb2 = __shfl_sync(0xFFFFFFFFu, s1, 31);
                supw[lane]      |= full0;
                supw[lane + 32] |= full1;
                if (lane == 0) supw[64] |= full2;
                u32 add0 = low_bits(m0, NEIGH - (int)nb0);
                if (lane == iseg) add0 |= ibit;
                if (add0) selw[lane] |= add0;
                u32 add1 = low_bits(m1, NEIGH - (int)nb1);
                if (lane + 32 == iseg) add1 |= ibit;
                if (add1) selw[lane + 32] |= add1;
                if (lane == 0) {
                    u32 add2 = low_bits(m2, NEIGH - (int)nb2);
                    if (iseg == 64) add2 |= ibit;
                    if (add2) selw[64] |= add2;
                }
            }
            __syncthreads();
            ++i; ++cnt;
        }
        __syncthreads();
    }

    // ---- parallel compactions ----
    if (warp == 0) {
        u32 v0 = __popc(~supw[lane]);
        u32 v1 = __popc(~supw[lane + 32]);
        u32 v2 = (lane == 0) ? __popc(~supw[64]) : 0;
        u32 s0 = warp_incl_scan(v0, lane);
        u32 t0 = __shfl_sync(0xFFFFFFFFu, s0, 31);
        u32 s1 = warp_incl_scan(v1, lane) + t0;
        u32 t1 = __shfl_sync(0xFFFFFFFFu, s1, 31);
        upref[lane]      = s0 - v0;
        upref[lane + 32] = s1 - v1;
        if (lane == 0) { upref[64] = t1; upref[65] = t1 + v2; }
    }
    if (warp == 1) {
        u32 v0 = __popc(selw[lane]);
        u32 v1 = __popc(selw[lane + 32]);
        u32 v2 = (lane == 0) ? __popc(selw[64]) : 0;
        u32 s0 = warp_incl_scan(v0, lane);
        u32 t0 = __shfl_sync(0xFFFFFFFFu, s0, 31);
        u32 s1 = warp_incl_scan(v1, lane) + t0;
        u32 t1 = __shfl_sync(0xFFFFFFFFu, s1, 31);
        spref[lane]      = s0 - v0;
        spref[lane + 32] = s1 - v1;
        if (lane == 0) { spref[64] = t1; spref[65] = t1 + v2; }
    }
    #pragma unroll
    for (int t = tid; t < MM; t += NTHR) unsup_idx[t] = (u16)(MM - 1);
    if (tid >= NTHR - TOTALS) sel_idx[tid - (NTHR - TOTALS)] = (u16)(MM - 1);
    __syncthreads();

    #pragma unroll
    for (int e2 = tid; e2 < MM; e2 += NTHR) {
        int s2 = e2 >> 5;
        u32 bit = 1u << (e2 & 31);
        u32 low = bit - 1u;
        u32 uw = ~supw[s2];
        if (uw & bit) unsup_idx[upref[s2] + __popc(uw & low)] = (u16)e2;
        u32 sw = selw[s2];
        if (sw & bit) sel_idx[spref[s2] + __popc(sw & low)] = (u16)e2;
    }
    __syncthreads();

    // ---- final index assembly + small outputs ----
    if (tid < KK) {
        int n_unsup = (int)upref[NSEG];
        int n_sel   = (int)spref[NSEG];
        int pad     = TOTALS - n_sel;

        int idxS;
        if (tid < NEGK) {
            int t = n_unsup - 1 - tid;
            if (t < 0) t = 0;
            if (t > MM - 1) t = MM - 1;
            idxS = unsup_idx[t];
        } else {
            int p = tid - NEGK;
            if (p < pad) idxS = unsup_idx[p];
            else {
                int q = p - pad;
                if (q > TOTALS - 1) q = TOTALS - 1;
                idxS = sel_idx[q];
            }
        }
        u32 orig = (u32)skeys[idxS];
        u32 rcv  = rc[orig];
        int r = rcv & 0xFF;
        int c = rcv >> 8;

        int gk = b * KK + tid;
        s_sel[tid] = (u32)(r * NN + c);

        out[SE_BASE + gk * 2 + 0] = (float)r;
        out[SE_BASE + gk * 2 + 1] = (float)(c + 1);

        size_t oidx = ((size_t)(b * NN + r) * NN + c) * 2;
        out[OFF_BASE + gk * 2 + 0] = offset_gt[oidx + 0];
        out[OFF_BASE + gk * 2 + 1] = offset_gt[oidx + 1];

        out[SC_BASE + gk] = tmap[(size_t)(b * NN + r) * NN + c];
    }
    __syncthreads();

    // ---- feature gather: batched loads (3 rounds of <=9 outstanding) ----
    {
        const float4* __restrict__ src4 = (const float4*)map2d;
        float4* __restrict__ dst4 = (float4*)(out + FEAT_BASE);
        const size_t bbase = (size_t)b * (NN * NN) * (DD / 4);
        const size_t obase = (size_t)b * KK * (DD / 4);
        const int total = KK * (DD / 4);            // 12928
        #pragma unroll 1
        for (int s0 = 0; s0 < 26; s0 += 9) {
            float4 v[9];
            #pragma unroll
            for (int m = 0; m < 9; ++m) {
                int s = s0 + m;
                int t = tid + s * NTHR;
                if (s < 26 && t < total) {
                    int row = t >> 7, q = t & 127;
                    v[m] = src4[bbase + (size_t)s_sel[row] * (DD / 4) + q];
                }
            }
            #pragma unroll
            for (int m = 0; m < 9; ++m) {
                int s = s0 + m;
                int t = tid + s * NTHR;
                if (s < 26 && t < total) {
                    int row = t >> 7, q = t & 127;
                    dst4[obase + (size_t)row * (DD / 4) + q] = v[m];
                }
            }
        }
    }
}

extern "C" void kernel_launch(void* const* d_in, const int* in_sizes, int n_in,
                              void* d_out, int out_size)
{
    const float* score_pred = (const float*)d_in[0];
    // d_in[1] = map2d_mask (deterministic triu — not needed)
    const float* map2d      = (const float*)d_in[2];
    const float* offset_gt  = (const float*)d_in[3];
    const float* tmap       = (const float*)d_in[4];
    float* out = (float*)d_out;

    presort_kernel<<<BATCH * 4, NTHR>>>(score_pred);
    merge_select_kernel<<<BATCH, NTHR>>>(map2d, offset_gt, tmap, out);
}